// round 14
// baseline (speedup 1.0000x reference)
#include <cuda_runtime.h>
#include <cuda_fp16.h>
#include <math.h>
#include <stdint.h>

#define BB 4
#define SS 2048
#define DD 1024
#define FFD 4096
#define ROWS (BB*SS)   // 8192
#define DSQ (DD*DD)
#define RD  (ROWS*DD)

// ---------------- scratch (device globals: no allocation) ----------------
__device__ __half g_W  [6*DSQ];      // transposed WQ1,WK1,WV1,WQ2,WK2,WV2 ([N,K]) fp16
__device__ __half g_Wf1[FFD*DD];     // Wff1^T fp16
__device__ __half g_Wf2[DD*FFD];     // Wff2^T fp16
__device__ __half g_yc [RD];         // y fp16
__device__ __half g_Zc [RD];         // Z fp16
__device__ __half g_QKV[3*RD];       // Q,K,V fp16
__device__ __half g_P  [(long)BB*SS*SS];  // scores -> probs fp16 (in-place softmax, 32 MB)
__device__ float  g_At [RD];
__device__ float  g_y1 [RD];
__device__ float  g_y2 [RD];
__device__ __half g_y1h[RD];
__device__ __half g_y2h[RD];
__device__ __half g_H  [ROWS*FFD];

// ---------------- helpers ----------------
__device__ __forceinline__ uint32_t smem_u32(const void* p) {
    uint32_t a;
    asm("{ .reg .u64 t; cvta.to.shared.u64 t, %1; cvt.u32.u64 %0, t; }" : "=r"(a) : "l"(p));
    return a;
}
__device__ __forceinline__ void mma_f16(float (&d)[4], const uint32_t (&a)[4], const uint32_t (&b)[2]) {
    asm volatile("mma.sync.aligned.m16n8k16.row.col.f32.f16.f16.f32 "
                 "{%0,%1,%2,%3}, {%4,%5,%6,%7}, {%8,%9}, {%0,%1,%2,%3};"
                 : "+f"(d[0]), "+f"(d[1]), "+f"(d[2]), "+f"(d[3])
                 : "r"(a[0]), "r"(a[1]), "r"(a[2]), "r"(a[3]), "r"(b[0]), "r"(b[1]));
}
#define CP16(dst, src) asm volatile("cp.async.cg.shared.global [%0], [%1], 16;" :: "r"(dst), "l"(src))
#define CP_COMMIT()    asm volatile("cp.async.commit_group;" ::: "memory")
#define CP_WAIT(n)     asm volatile("cp.async.wait_group %0;" :: "n"(n) : "memory")
#define LDSM4(d0,d1,d2,d3,a) \
    asm volatile("ldmatrix.sync.aligned.m8n8.x4.shared.b16 {%0,%1,%2,%3}, [%4];" \
                 : "=r"(d0),"=r"(d1),"=r"(d2),"=r"(d3) : "r"(a))
#define LDSM4T(d0,d1,d2,d3,a) \
    asm volatile("ldmatrix.sync.aligned.m8n8.x4.trans.shared.b16 {%0,%1,%2,%3}, [%4];" \
                 : "=r"(d0),"=r"(d1),"=r"(d2),"=r"(d3) : "r"(a))

// smem: per stage A[128 rows x 144B]; B: TB [128 x 144B] or NN [64 k-rows x 272B]
#define RBYTES  144
#define NBYTES  272
#define A_BYTES (128*RBYTES)            // 18432
#define B_BYTES 18432                   // max(128*144, 64*272=17408)
#define STAGE_BYTES (A_BYTES + B_BYTES) // 36864
#define SMEM_BYTES (3*STAGE_BYTES)      // 110592  (x2 CTAs = 221184 <= 228KB)

template<bool TRB>
__device__ __forceinline__ void issue_stage(uint32_t sA, uint32_t sB,
    const __half* __restrict__ A, const __half* __restrict__ Bm,
    int m0, int n0, int k0, int N, int K, int tid)
{
    #pragma unroll
    for (int i = 0; i < 4; ++i) {            // A: 128 rows x 8 16B-chunks (64 halves of k)
        int pos = tid + i * 256;
        int row = pos >> 3, kq = pos & 7;
        CP16(sA + (uint32_t)(row * RBYTES + kq * 16),
             &A[(long)(m0 + row) * K + k0 + kq * 8]);
    }
    if (TRB) {
        #pragma unroll
        for (int i = 0; i < 4; ++i) {        // B[N,K]: 128 n-rows x 8 chunks
            int pos = tid + i * 256;
            int row = pos >> 3, kq = pos & 7;
            CP16(sB + (uint32_t)(row * RBYTES + kq * 16),
                 &Bm[(long)(n0 + row) * K + k0 + kq * 8]);
        }
    } else {
        #pragma unroll
        for (int i = 0; i < 4; ++i) {        // B[K,N]: 64 k-rows x 16 chunks (128 halves of n)
            int pos = tid + i * 256;
            int row = pos >> 4, cq = pos & 15;
            CP16(sB + (uint32_t)(row * NBYTES + cq * 16),
                 &Bm[(long)(k0 + row) * N + n0 + cq * 8]);
        }
    }
    CP_COMMIT();
}

// ---------------- fp16 HMMA GEMM, persistent tiles: C[M,N] = A[M,K]*op(B) ----------------
// Tile 128x128xK64, 8 warps, 2 CTA/SM, grid = 2*SMs, CTA loops over linear tile ids.
// TRB: B is [N,K] (C=A*B^T). else B is [K,N] (C=A*B, trans-ldmatrix path).
// CAUSAL: enumerate only lower-triangle tiles. CLIPK: K stops at m0+128, heavy rows first.
template<typename OT, bool TRB, bool CAUSAL, bool BIAS, bool RELU, bool CLIPK>
__global__ void __launch_bounds__(256, 2)
tgemm(const __half* __restrict__ A0, const __half* __restrict__ B0,
      const float* __restrict__ bias, OT* __restrict__ C0,
      int N, int K, float scale, long sA_, long sB_, long sC_,
      int ntx, int nty, int nz)
{
    const int tpz = CAUSAL ? (nty * (nty + 1)) / 2 : ntx * nty;
    const int ntiles = tpz * nz;

    extern __shared__ __align__(16) char smc[];
    const uint32_t sb = smem_u32(smc);
    const int tid = threadIdx.x, lane = tid & 31, wid = tid >> 5;
    const int wm = (wid & 1) * 64;          // 2 warps in M
    const int wn = (wid >> 1) * 32;         // 4 warps in N
    const int gid = lane >> 2, tg = lane & 3;
    // ldmatrix per-lane offsets (bytes)
    const uint32_t offA = (uint32_t)(wm + (lane & 15)) * RBYTES + ((lane >> 4) & 1) * 16;
    const uint32_t offB = (uint32_t)(wn + (lane & 7) + ((lane >> 4) & 1) * 8) * RBYTES
                        + ((lane >> 3) & 1) * 16;                      // TB path
    const uint32_t offBn = (uint32_t)((lane & 7) + ((lane >> 3) & 1) * 8) * NBYTES
                         + (uint32_t)wn * 2 + ((lane >> 4) & 1) * 16;  // NN path

    for (int t = blockIdx.x; t < ntiles; t += gridDim.x) {
        const int z = t / tpz;
        const int r = t - z * tpz;
        int by, bx;
        if (CAUSAL) {
            by = (int)((sqrtf(8.0f * (float)r + 1.0f) - 1.0f) * 0.5f);
            while ((by + 1) * (by + 2) / 2 <= r) ++by;
            while (by * (by + 1) / 2 > r) --by;
            bx = r - by * (by + 1) / 2;
        } else if (CLIPK) {
            by = nty - 1 - (r / ntx);       // heavy rows first
            bx = r - (nty - 1 - by) * ntx;
        } else {
            by = r / ntx;
            bx = r - by * ntx;
        }
        const int m0 = by * 128, n0 = bx * 128;
        const __half* A  = A0 + (long)z * sA_;
        const __half* Bm = B0 + (long)z * sB_;
        OT* C = C0 + (long)z * sC_;

        int Keff = K;
        if (CLIPK) { int km = m0 + 128; Keff = (km < K) ? km : K; }
        const int nch = Keff >> 6;          // K-chunks of 64

        float acc[4][4][4];
        #pragma unroll
        for (int mt = 0; mt < 4; ++mt)
            #pragma unroll
            for (int nt = 0; nt < 4; ++nt)
                #pragma unroll
                for (int j = 0; j < 4; ++j) acc[mt][nt][j] = 0.0f;

        issue_stage<TRB>(sb, sb + A_BYTES, A, Bm, m0, n0, 0, N, K, tid);
        if (nch > 1)
            issue_stage<TRB>(sb + STAGE_BYTES, sb + STAGE_BYTES + A_BYTES, A, Bm, m0, n0, 64, N, K, tid);

        for (int c = 0; c < nch; ++c) {
            if (c + 2 <= nch) CP_WAIT(1); else CP_WAIT(0);
            __syncthreads();
            if (c + 2 < nch) {
                const uint32_t off = (uint32_t)((c + 2) % 3) * STAGE_BYTES;
                issue_stage<TRB>(sb + off, sb + off + A_BYTES, A, Bm, m0, n0, (c + 2) << 6, N, K, tid);
            }
            const uint32_t stA = sb + (uint32_t)(c % 3) * STAGE_BYTES;
            const uint32_t stB = stA + A_BYTES;

            auto load_b = [&](uint32_t (&b)[4][2], int ks) {
                if (TRB) {
                    const uint32_t kby = (uint32_t)ks * 32;
                    #pragma unroll
                    for (int ntp = 0; ntp < 2; ++ntp)
                        LDSM4(b[2*ntp][0], b[2*ntp][1], b[2*ntp+1][0], b[2*ntp+1][1],
                              stB + offB + (uint32_t)(ntp * 16 * RBYTES) + kby);
                } else {
                    const uint32_t kof = (uint32_t)(ks * 16) * NBYTES;
                    #pragma unroll
                    for (int ntp = 0; ntp < 2; ++ntp)
                        LDSM4T(b[2*ntp][0], b[2*ntp][1], b[2*ntp+1][0], b[2*ntp+1][1],
                               stB + offBn + kof + (uint32_t)(ntp * 32));
                }
            };

            uint32_t bf[2][4][2];
            load_b(bf[0], 0);
            #pragma unroll
            for (int ks = 0; ks < 4; ++ks) {
                if (ks < 3) load_b(bf[(ks + 1) & 1], ks + 1);
                const uint32_t kby = (uint32_t)ks * 32;
                #pragma unroll
                for (int mt = 0; mt < 4; ++mt) {
                    uint32_t a[4];
                    LDSM4(a[0], a[1], a[2], a[3],
                          stA + offA + (uint32_t)(mt * 16 * RBYTES) + kby);
                    #pragma unroll
                    for (int nt = 0; nt < 4; ++nt) mma_f16(acc[mt][nt], a, bf[ks & 1][nt]);
                }
            }
        }

        // ---- epilogue ----
        #pragma unroll
        for (int mt = 0; mt < 4; ++mt) {
            const long r0 = m0 + wm + mt * 16 + gid;
            #pragma unroll
            for (int nt = 0; nt < 4; ++nt) {
                const int col = n0 + wn + nt * 8 + 2 * tg;
                float v0 = acc[mt][nt][0] * scale;
                float v1 = acc[mt][nt][1] * scale;
                float v2 = acc[mt][nt][2] * scale;
                float v3 = acc[mt][nt][3] * scale;
                if (BIAS) {
                    float b0 = bias[col], b1 = bias[col + 1];
                    v0 += b0; v1 += b1; v2 += b0; v3 += b1;
                }
                if (RELU) {
                    v0 = fmaxf(v0, 0.0f); v1 = fmaxf(v1, 0.0f);
                    v2 = fmaxf(v2, 0.0f); v3 = fmaxf(v3, 0.0f);
                }
                if constexpr (sizeof(OT) == 2) {
                    *(__half2*)&C[r0 * (long)N + col]       = __floats2half2_rn(v0, v1);
                    *(__half2*)&C[(r0 + 8) * (long)N + col] = __floats2half2_rn(v2, v3);
                } else {
                    *(float2*)&C[r0 * (long)N + col]       = make_float2(v0, v1);
                    *(float2*)&C[(r0 + 8) * (long)N + col] = make_float2(v2, v3);
                }
            }
        }
        __syncthreads();   // all warps done with smem before next tile's cp.async
    }
}

// ---------------- fp32 -> fp16 copies, two tensors in one launch ----------------
__global__ void cvt2_h(const float4* __restrict__ s0, uint2* __restrict__ d0,
                       const float4* __restrict__ s1, uint2* __restrict__ d1, int n4)
{
    const float4* s = blockIdx.z ? s1 : s0;
    uint2* d = blockIdx.z ? d1 : d0;
    for (int i = blockIdx.x * blockDim.x + threadIdx.x; i < n4; i += gridDim.x * blockDim.x) {
        float4 v = s[i];
        __half2 h0 = __floats2half2_rn(v.x, v.y);
        __half2 h1 = __floats2half2_rn(v.z, v.w);
        uint2 u;
        u.x = *(const uint32_t*)&h0;
        u.y = *(const uint32_t*)&h1;
        d[i] = u;
    }
}

// ---------------- transpose to fp16: src[R,C] -> dst[C,R] ----------------
__global__ void trans_kernel(const float* __restrict__ src, __half* __restrict__ dst,
                             int R, int C)
{
    __shared__ float t[32][33];
    const int c0 = blockIdx.x * 32, r0 = blockIdx.y * 32;
    const int x = threadIdx.x, y = threadIdx.y;      // 32x8
    #pragma unroll
    for (int i = 0; i < 32; i += 8)
        t[y + i][x] = src[(long)(r0 + y + i) * C + c0 + x];
    __syncthreads();
    #pragma unroll
    for (int i = 0; i < 32; i += 8)
        dst[(long)(c0 + y + i) * R + r0 + x] = __float2half_rn(t[x][y + i]);
}

// ---------------- batched 1024x1024 transpose of the six attention weights ----------------
struct Ptr6 { const float* p[6]; };
__global__ void trans6_kernel(Ptr6 src, __half* __restrict__ dst)
{
    __shared__ float t[32][33];
    const float* s = src.p[blockIdx.z];
    __half* d = dst + (long)blockIdx.z * DSQ;
    const int c0 = blockIdx.x * 32, r0 = blockIdx.y * 32;
    const int x = threadIdx.x, y = threadIdx.y;
    #pragma unroll
    for (int i = 0; i < 32; i += 8)
        t[y + i][x] = s[(long)(r0 + y + i) * DD + c0 + x];
    __syncthreads();
    #pragma unroll
    for (int i = 0; i < 32; i += 8)
        d[(long)(c0 + y + i) * DD + r0 + x] = __float2half_rn(t[x][y + i]);
}

// ---------------- in-place row softmax on fp16 scores/probs ----------------
__global__ void softmax_kernel(__half* __restrict__ P, int Sq, int Sk, int causal)
{
    const long row = blockIdx.x;
    const int  q   = (int)(row % Sq);
    const int  valid = causal ? (q + 1) : Sk;
    const int  wlim  = causal ? (((q >> 7) + 1) << 7) : Sk;
    __half* p = P + row * (long)Sk;
    const int tid = threadIdx.x;
    const int k0 = tid * 8;                     // Sk = 2048 = 256*8
    __shared__ float red[256];

    uint4 u = ((const uint4*)p)[tid];
    const __half2* hp = (const __half2*)&u;
    float r[8];
    #pragma unroll
    for (int j = 0; j < 4; ++j) {
        float2 f = __half22float2(hp[j]);
        r[2*j] = f.x; r[2*j+1] = f.y;
    }
    float m = -3.0e38f;
    #pragma unroll
    for (int i = 0; i < 8; ++i) {
        if (k0 + i >= valid) r[i] = -3.0e38f;
        m = fmaxf(m, r[i]);
    }
    red[tid] = m; __syncthreads();
    for (int st = 128; st > 0; st >>= 1) {
        if (tid < st) red[tid] = fmaxf(red[tid], red[tid + st]);
        __syncthreads();
    }
    m = red[0]; __syncthreads();

    float s = 0.0f;
    #pragma unroll
    for (int i = 0; i < 8; ++i) {
        r[i] = (r[i] > -1.0e38f) ? __expf(r[i] - m) : 0.0f;
        s += r[i];
    }
    red[tid] = s; __syncthreads();
    for (int st = 128; st > 0; st >>= 1) {
        if (tid < st) red[tid] += red[tid + st];
        __syncthreads();
    }
    const float inv = 1.0f / red[0];

    if (k0 < wlim) {                            // 8 | 128 so the whole uint4 is in/out
        uint4 o;
        __half2* ho = (__half2*)&o;
        #pragma unroll
        for (int j = 0; j < 4; ++j)
            ho[j] = __floats2half2_rn(r[2*j] * inv, r[2*j+1] * inv);
        ((uint4*)p)[tid] = o;
    }
}

// ---------------- out = LayerNorm(R + X)*gamma + beta; optional fp16 copy ----------------
template<bool HC>
__global__ void add_ln_kernel(const float* __restrict__ R, const float* __restrict__ X,
                              const float* __restrict__ g, const float* __restrict__ b,
                              float* __restrict__ O, __half* __restrict__ Oh)
{
    const int  tid = threadIdx.x;
    const long row = blockIdx.x;
    const float4 rv = ((const float4*)(R + row * DD))[tid];
    const float4 xv = ((const float4*)(X + row * DD))[tid];
    float v[4] = {rv.x + xv.x, rv.y + xv.y, rv.z + xv.z, rv.w + xv.w};

    float s  = v[0] + v[1] + v[2] + v[3];
    float sq = v[0]*v[0] + v[1]*v[1] + v[2]*v[2] + v[3]*v[3];
    __shared__ float rs[256], rq[256];
    rs[tid] = s; rq[tid] = sq; __syncthreads();
    for (int st = 128; st > 0; st >>= 1) {
        if (tid < st) { rs[tid] += rs[tid + st]; rq[tid] += rq[tid + st]; }
        __syncthreads();
    }
    const float mu  = rs[0] * (1.0f / DD);
    const float var = rq[0] * (1.0f / DD) - mu * mu;
    const float inv = rsqrtf(var + 1e-5f);

    const float4 gv = ((const float4*)g)[tid];
    const float4 bv = ((const float4*)b)[tid];
    float4 o;
    o.x = (v[0] - mu) * inv * gv.x + bv.x;
    o.y = (v[1] - mu) * inv * gv.y + bv.y;
    o.z = (v[2] - mu) * inv * gv.z + bv.z;
    o.w = (v[3] - mu) * inv * gv.w + bv.w;
    ((float4*)(O + row * DD))[tid] = o;
    if (HC) {
        __half2 h0 = __floats2half2_rn(o.x, o.y);
        __half2 h1 = __floats2half2_rn(o.z, o.w);
        uint2 u;
        u.x = *(const uint32_t*)&h0;
        u.y = *(const uint32_t*)&h1;
        ((uint2*)(Oh + row * DD))[tid] = u;
    }
}

// ---------------- launch ----------------
extern "C" void kernel_launch(void* const* d_in, const int* in_sizes, int n_in,
                              void* d_out, int out_size)
{
    (void)in_sizes; (void)n_in; (void)out_size;
    const float* y    = (const float*)d_in[0];
    const float* Z    = (const float*)d_in[1];
    const float* Wff1 = (const float*)d_in[8];
    const float* bff1 = (const float*)d_in[9];
    const float* Wff2 = (const float*)d_in[10];
    const float* bff2 = (const float*)d_in[11];
    const float* g1   = (const float*)d_in[12];
    const float* be1  = (const float*)d_in[13];
    const float* g2   = (const float*)d_in[14];
    const float* be2  = (const float*)d_in[15];
    const float* g3   = (const float*)d_in[16];
    const float* be3  = (const float*)d_in[17];
    float* out = (float*)d_out;

    __half *W, *Wf1, *Wf2, *yc, *Zc, *QKV, *P, *y1h, *y2h, *H;
    float *At, *y1, *y2;
    cudaGetSymbolAddress((void**)&W,   g_W);
    cudaGetSymbolAddress((void**)&Wf1, g_Wf1);
    cudaGetSymbolAddress((void**)&Wf2, g_Wf2);
    cudaGetSymbolAddress((void**)&yc,  g_yc);
    cudaGetSymbolAddress((void**)&Zc,  g_Zc);
    cudaGetSymbolAddress((void**)&QKV, g_QKV);
    cudaGetSymbolAddress((void**)&P,   g_P);
    cudaGetSymbolAddress((void**)&At,  g_At);
    cudaGetSymbolAddress((void**)&y1,  g_y1);
    cudaGetSymbolAddress((void**)&y2,  g_y2);
    cudaGetSymbolAddress((void**)&y1h, g_y1h);
    cudaGetSymbolAddress((void**)&y2h, g_y2h);
    cudaGetSymbolAddress((void**)&H,   g_H);

    cudaFuncSetAttribute(tgemm<__half,true, false,false,false,false>, cudaFuncAttributeMaxDynamicSharedMemorySize, SMEM_BYTES);
    cudaFuncSetAttribute(tgemm<__half,true, true, false,false,false>, cudaFuncAttributeMaxDynamicSharedMemorySize, SMEM_BYTES);
    cudaFuncSetAttribute(tgemm<float, false,false,false,false,true >, cudaFuncAttributeMaxDynamicSharedMemorySize, SMEM_BYTES);
    cudaFuncSetAttribute(tgemm<float, false,false,false,false,false>, cudaFuncAttributeMaxDynamicSharedMemorySize, SMEM_BYTES);
    cudaFuncSetAttribute(tgemm<__half,true, false,true, true, false>, cudaFuncAttributeMaxDynamicSharedMemorySize, SMEM_BYTES);
    cudaFuncSetAttribute(tgemm<float, true, false,true, false,false>, cudaFuncAttributeMaxDynamicSharedMemorySize, SMEM_BYTES);

    int nsm = 148;
    cudaDeviceGetAttribute(&nsm, cudaDevAttrMultiProcessorCount, 0);
    const int gP = 2 * nsm;                       // persistent grid (2 CTA/SM)

    const dim3 tht(32, 8);
    // ---- pre-pass: fp16 copies of activations; transposed fp16 weights ----
    cvt2_h<<<dim3(1184, 1, 2), 256>>>((const float4*)y, (uint2*)yc,
                                      (const float4*)Z, (uint2*)Zc, RD / 4);
    Ptr6 w6 = {{ (const float*)d_in[2], (const float*)d_in[3], (const float*)d_in[4],
                 (const float*)d_in[5], (const float*)d_in[6], (const float*)d_in[7] }};
    trans6_kernel<<<dim3(32, 32, 6), tht>>>(w6, W);
    trans_kernel<<<dim3(128, 32), tht>>>(Wff1, Wf1, DD, FFD);   // -> [FF,D]
    trans_kernel<<<dim3(32, 128), tht>>>(Wff2, Wf2, FFD, DD);   // -> [D,FF]

    const dim3 th(256);
    const float ascale = 1.0f / 32.0f;            // 1/sqrt(1024)
    const long sQK = (long)SS * DD;
    const long sSc = (long)SS * SS;
    __half* Q  = QKV;
    __half* Kp = QKV + (long)RD;
    __half* V  = QKV + 2L * RD;

    // ---- block 1: causal self-attention + add&norm ----
    tgemm<__half,true, false,false,false,false><<<gP, th, SMEM_BYTES>>>(yc, W, nullptr, QKV, DD, DD, 1.0f, 0, DSQ, RD, 8, 64, 3);
    tgemm<__half,true, true, false,false,false><<<gP, th, SMEM_BYTES>>>(Q, Kp, nullptr, P, SS, DD, ascale, sQK, sQK, sSc, 16, 16, 4);
    softmax_kernel<<<BB * SS, 256>>>(P, SS, SS, 1);
    tgemm<float, false,false,false,false,true ><<<gP, th, SMEM_BYTES>>>(P, V, nullptr, At, DD, SS, 1.0f, sSc, sQK, sQK, 8, 16, 4);
    add_ln_kernel<true><<<ROWS, 256>>>(y, At, g1, be1, y1, y1h);

    // ---- block 2: cross-attention + add&norm ----
    tgemm<__half,true, false,false,false,false><<<gP, th, SMEM_BYTES>>>(y1h, W + 3L*DSQ, nullptr, Q,  DD, DD, 1.0f, 0, DSQ, RD, 8, 64, 1);
    tgemm<__half,true, false,false,false,false><<<gP, th, SMEM_BYTES>>>(Zc,  W + 4L*DSQ, nullptr, Kp, DD, DD, 1.0f, 0, DSQ, RD, 8, 64, 2);
    tgemm<__half,true, false,false,false,false><<<gP, th, SMEM_BYTES>>>(Q, Kp, nullptr, P, SS, DD, ascale, sQK, sQK, sSc, 16, 16, 4);
    softmax_kernel<<<BB * SS, 256>>>(P, SS, SS, 0);
    tgemm<float, false,false,false,false,false><<<gP, th, SMEM_BYTES>>>(P, V, nullptr, At, DD, SS, 1.0f, sSc, sQK, sQK, 8, 16, 4);
    add_ln_kernel<true><<<ROWS, 256>>>(y1, At, g2, be2, y2, y2h);

    // ---- FFN + add&norm ----
    tgemm<__half,true, false,true, true, false><<<gP, th, SMEM_BYTES>>>(y2h, Wf1, bff1, H,  FFD, DD,  1.0f, 0, 0, 0, 32, 64, 1);
    tgemm<float, true, false,true, false,false><<<gP, th, SMEM_BYTES>>>(H,   Wf2, bff2, At, DD,  FFD, 1.0f, 0, 0, 0, 8, 64, 1);
    add_ln_kernel<false><<<ROWS, 256>>>(y2, At, g3, be3, out, nullptr);
}

// round 15
// speedup vs baseline: 1.0906x; 1.0906x over previous
#include <cuda_runtime.h>
#include <cuda_fp16.h>
#include <math.h>
#include <stdint.h>

#define BB 4
#define SS 2048
#define DD 1024
#define FFD 4096
#define ROWS (BB*SS)   // 8192
#define DSQ (DD*DD)
#define RD  (ROWS*DD)

// ---------------- scratch (device globals: no allocation) ----------------
__device__ __half g_W  [6*DSQ];      // transposed WQ1,WK1,WV1,WQ2,WK2,WV2 ([N,K]) fp16
__device__ __half g_Wf1[FFD*DD];     // Wff1^T fp16
__device__ __half g_Wf2[DD*FFD];     // Wff2^T fp16
__device__ __half g_yc [RD];         // y fp16
__device__ __half g_Zc [RD];         // Z fp16
__device__ __half g_QKV[3*RD];       // Q,K,V fp16
__device__ __half g_P  [(long)BB*SS*SS];  // scores -> probs fp16 (in-place softmax, 32 MB)
__device__ __half g_At [RD];         // attention / FFN branch output, fp16
__device__ float  g_y1 [RD];
__device__ float  g_y2 [RD];
__device__ __half g_y1h[RD];
__device__ __half g_y2h[RD];
__device__ __half g_H  [ROWS*FFD];

// ---------------- helpers ----------------
__device__ __forceinline__ uint32_t smem_u32(const void* p) {
    uint32_t a;
    asm("{ .reg .u64 t; cvta.to.shared.u64 t, %1; cvt.u32.u64 %0, t; }" : "=r"(a) : "l"(p));
    return a;
}
__device__ __forceinline__ void mma_f16(float (&d)[4], const uint32_t (&a)[4], const uint32_t (&b)[2]) {
    asm volatile("mma.sync.aligned.m16n8k16.row.col.f32.f16.f16.f32 "
                 "{%0,%1,%2,%3}, {%4,%5,%6,%7}, {%8,%9}, {%0,%1,%2,%3};"
                 : "+f"(d[0]), "+f"(d[1]), "+f"(d[2]), "+f"(d[3])
                 : "r"(a[0]), "r"(a[1]), "r"(a[2]), "r"(a[3]), "r"(b[0]), "r"(b[1]));
}
#define CP16(dst, src) asm volatile("cp.async.cg.shared.global [%0], [%1], 16;" :: "r"(dst), "l"(src))
#define CP_COMMIT()    asm volatile("cp.async.commit_group;" ::: "memory")
#define CP_WAIT(n)     asm volatile("cp.async.wait_group %0;" :: "n"(n) : "memory")
#define LDSM4(d0,d1,d2,d3,a) \
    asm volatile("ldmatrix.sync.aligned.m8n8.x4.shared.b16 {%0,%1,%2,%3}, [%4];" \
                 : "=r"(d0),"=r"(d1),"=r"(d2),"=r"(d3) : "r"(a))
#define LDSM4T(d0,d1,d2,d3,a) \
    asm volatile("ldmatrix.sync.aligned.m8n8.x4.trans.shared.b16 {%0,%1,%2,%3}, [%4];" \
                 : "=r"(d0),"=r"(d1),"=r"(d2),"=r"(d3) : "r"(a))

// smem: per stage A[128 rows x 144B]; B: TB [128 x 144B] or NN [64 k-rows x 272B]
#define RBYTES  144
#define NBYTES  272
#define A_BYTES (128*RBYTES)            // 18432
#define B_BYTES 18432                   // max(128*144, 64*272=17408)
#define STAGE_BYTES (A_BYTES + B_BYTES) // 36864
#define SMEM_BYTES (3*STAGE_BYTES)      // 110592  (x2 CTAs = 221184 <= 228KB)

template<bool TRB>
__device__ __forceinline__ void issue_stage(uint32_t sA, uint32_t sB,
    const __half* __restrict__ A, const __half* __restrict__ Bm,
    int m0, int n0, int k0, int N, int K, int tid)
{
    #pragma unroll
    for (int i = 0; i < 4; ++i) {            // A: 128 rows x 8 16B-chunks (64 halves of k)
        int pos = tid + i * 256;
        int row = pos >> 3, kq = pos & 7;
        CP16(sA + (uint32_t)(row * RBYTES + kq * 16),
             &A[(long)(m0 + row) * K + k0 + kq * 8]);
    }
    if (TRB) {
        #pragma unroll
        for (int i = 0; i < 4; ++i) {        // B[N,K]: 128 n-rows x 8 chunks
            int pos = tid + i * 256;
            int row = pos >> 3, kq = pos & 7;
            CP16(sB + (uint32_t)(row * RBYTES + kq * 16),
                 &Bm[(long)(n0 + row) * K + k0 + kq * 8]);
        }
    } else {
        #pragma unroll
        for (int i = 0; i < 4; ++i) {        // B[K,N]: 64 k-rows x 16 chunks (128 halves of n)
            int pos = tid + i * 256;
            int row = pos >> 4, cq = pos & 15;
            CP16(sB + (uint32_t)(row * NBYTES + cq * 16),
                 &Bm[(long)(k0 + row) * N + n0 + cq * 8]);
        }
    }
    CP_COMMIT();
}

// ---------------- fp16 HMMA GEMM: C[M,N] = A[M,K]*op(B), tile 128x128xK64, 8 warps, 2 CTA/SM
// TRB: B is [N,K] (C=A*B^T). else B is [K,N] (C=A*B, trans-ldmatrix path).
// CAUSAL: skip tiles above diagonal. CLIPK: K stops at m0+128 (+ heavy-first y order).
template<typename OT, bool TRB, bool CAUSAL, bool BIAS, bool RELU, bool CLIPK>
__global__ void __launch_bounds__(256, 2)
tgemm(const __half* __restrict__ A, const __half* __restrict__ Bm,
      const float* __restrict__ bias, OT* __restrict__ C,
      int N, int K, float scale, long sA_, long sB_, long sC_)
{
    const int by = CLIPK ? ((int)gridDim.y - 1 - (int)blockIdx.y) : (int)blockIdx.y;
    const int m0 = by * 128, n0 = blockIdx.x * 128;
    if (CAUSAL && n0 > m0 + 127) return;
    A  += (long)blockIdx.z * sA_;
    Bm += (long)blockIdx.z * sB_;
    C  += (long)blockIdx.z * sC_;

    extern __shared__ __align__(16) char smc[];
    const uint32_t sb = smem_u32(smc);
    const int tid = threadIdx.x, lane = tid & 31, wid = tid >> 5;
    const int wm = (wid & 1) * 64;          // 2 warps in M
    const int wn = (wid >> 1) * 32;         // 4 warps in N
    const int gid = lane >> 2, tg = lane & 3;
    // ldmatrix per-lane offsets (bytes)
    const uint32_t offA = (uint32_t)(wm + (lane & 15)) * RBYTES + ((lane >> 4) & 1) * 16;
    const uint32_t offB = (uint32_t)(wn + (lane & 7) + ((lane >> 4) & 1) * 8) * RBYTES
                        + ((lane >> 3) & 1) * 16;                      // TB path
    const uint32_t offBn = (uint32_t)((lane & 7) + ((lane >> 3) & 1) * 8) * NBYTES
                         + (uint32_t)wn * 2 + ((lane >> 4) & 1) * 16;  // NN path

    int Keff = K;
    if (CLIPK) { int km = m0 + 128; Keff = (km < K) ? km : K; }
    const int nch = Keff >> 6;              // K-chunks of 64

    float acc[4][4][4];
    #pragma unroll
    for (int mt = 0; mt < 4; ++mt)
        #pragma unroll
        for (int nt = 0; nt < 4; ++nt)
            #pragma unroll
            for (int j = 0; j < 4; ++j) acc[mt][nt][j] = 0.0f;

    issue_stage<TRB>(sb, sb + A_BYTES, A, Bm, m0, n0, 0, N, K, tid);
    if (nch > 1)
        issue_stage<TRB>(sb + STAGE_BYTES, sb + STAGE_BYTES + A_BYTES, A, Bm, m0, n0, 64, N, K, tid);

    for (int c = 0; c < nch; ++c) {
        if (c + 2 <= nch) CP_WAIT(1); else CP_WAIT(0);
        __syncthreads();
        if (c + 2 < nch) {
            const uint32_t off = (uint32_t)((c + 2) % 3) * STAGE_BYTES;
            issue_stage<TRB>(sb + off, sb + off + A_BYTES, A, Bm, m0, n0, (c + 2) << 6, N, K, tid);
        }
        const uint32_t stA = sb + (uint32_t)(c % 3) * STAGE_BYTES;
        const uint32_t stB = stA + A_BYTES;

        // B-fragment loader for k-step ks (double-buffered across ksteps)
        auto load_b = [&](uint32_t (&b)[4][2], int ks) {
            if (TRB) {
                const uint32_t kby = (uint32_t)ks * 32;
                #pragma unroll
                for (int ntp = 0; ntp < 2; ++ntp)
                    LDSM4(b[2*ntp][0], b[2*ntp][1], b[2*ntp+1][0], b[2*ntp+1][1],
                          stB + offB + (uint32_t)(ntp * 16 * RBYTES) + kby);
            } else {
                const uint32_t kof = (uint32_t)(ks * 16) * NBYTES;
                #pragma unroll
                for (int ntp = 0; ntp < 2; ++ntp)
                    LDSM4T(b[2*ntp][0], b[2*ntp][1], b[2*ntp+1][0], b[2*ntp+1][1],
                           stB + offBn + kof + (uint32_t)(ntp * 32));
            }
        };

        uint32_t bf[2][4][2];
        load_b(bf[0], 0);
        #pragma unroll
        for (int ks = 0; ks < 4; ++ks) {
            if (ks < 3) load_b(bf[(ks + 1) & 1], ks + 1);
            const uint32_t kby = (uint32_t)ks * 32;
            #pragma unroll
            for (int mt = 0; mt < 4; ++mt) {
                uint32_t a[4];
                LDSM4(a[0], a[1], a[2], a[3],
                      stA + offA + (uint32_t)(mt * 16 * RBYTES) + kby);
                #pragma unroll
                for (int nt = 0; nt < 4; ++nt) mma_f16(acc[mt][nt], a, bf[ks & 1][nt]);
            }
        }
    }

    // ---- epilogue ----
    #pragma unroll
    for (int mt = 0; mt < 4; ++mt) {
        const long r0 = m0 + wm + mt * 16 + gid;
        #pragma unroll
        for (int nt = 0; nt < 4; ++nt) {
            const int col = n0 + wn + nt * 8 + 2 * tg;
            float v0 = acc[mt][nt][0] * scale;
            float v1 = acc[mt][nt][1] * scale;
            float v2 = acc[mt][nt][2] * scale;
            float v3 = acc[mt][nt][3] * scale;
            if (BIAS) {
                float b0 = bias[col], b1 = bias[col + 1];
                v0 += b0; v1 += b1; v2 += b0; v3 += b1;
            }
            if (RELU) {
                v0 = fmaxf(v0, 0.0f); v1 = fmaxf(v1, 0.0f);
                v2 = fmaxf(v2, 0.0f); v3 = fmaxf(v3, 0.0f);
            }
            if constexpr (sizeof(OT) == 2) {
                *(__half2*)&C[r0 * (long)N + col]       = __floats2half2_rn(v0, v1);
                *(__half2*)&C[(r0 + 8) * (long)N + col] = __floats2half2_rn(v2, v3);
            } else {
                *(float2*)&C[r0 * (long)N + col]       = make_float2(v0, v1);
                *(float2*)&C[(r0 + 8) * (long)N + col] = make_float2(v2, v3);
            }
        }
    }
}

// ---------------- fp32 -> fp16 copies, two tensors in one launch ----------------
__global__ void cvt2_h(const float4* __restrict__ s0, uint2* __restrict__ d0,
                       const float4* __restrict__ s1, uint2* __restrict__ d1, int n4)
{
    const float4* s = blockIdx.z ? s1 : s0;
    uint2* d = blockIdx.z ? d1 : d0;
    for (int i = blockIdx.x * blockDim.x + threadIdx.x; i < n4; i += gridDim.x * blockDim.x) {
        float4 v = s[i];
        __half2 h0 = __floats2half2_rn(v.x, v.y);
        __half2 h1 = __floats2half2_rn(v.z, v.w);
        uint2 u;
        u.x = *(const uint32_t*)&h0;
        u.y = *(const uint32_t*)&h1;
        d[i] = u;
    }
}

// ---------------- transpose to fp16: src[R,C] -> dst[C,R] ----------------
__global__ void trans_kernel(const float* __restrict__ src, __half* __restrict__ dst,
                             int R, int C)
{
    __shared__ float t[32][33];
    const int c0 = blockIdx.x * 32, r0 = blockIdx.y * 32;
    const int x = threadIdx.x, y = threadIdx.y;      // 32x8
    #pragma unroll
    for (int i = 0; i < 32; i += 8)
        t[y + i][x] = src[(long)(r0 + y + i) * C + c0 + x];
    __syncthreads();
    #pragma unroll
    for (int i = 0; i < 32; i += 8)
        dst[(long)(c0 + y + i) * R + r0 + x] = __float2half_rn(t[x][y + i]);
}

// ---------------- batched 1024x1024 transpose of the six attention weights ----------------
struct Ptr6 { const float* p[6]; };
__global__ void trans6_kernel(Ptr6 src, __half* __restrict__ dst)
{
    __shared__ float t[32][33];
    const float* s = src.p[blockIdx.z];
    __half* d = dst + (long)blockIdx.z * DSQ;
    const int c0 = blockIdx.x * 32, r0 = blockIdx.y * 32;
    const int x = threadIdx.x, y = threadIdx.y;
    #pragma unroll
    for (int i = 0; i < 32; i += 8)
        t[y + i][x] = s[(long)(r0 + y + i) * DD + c0 + x];
    __syncthreads();
    #pragma unroll
    for (int i = 0; i < 32; i += 8)
        d[(long)(c0 + y + i) * DD + r0 + x] = __float2half_rn(t[x][y + i]);
}

// ---------------- in-place row softmax on fp16 scores/probs ----------------
// One uint4 (8 halves) per thread; causal: loads/stores only below the 128-aligned limit.
__global__ void softmax_kernel(__half* __restrict__ P, int Sq, int Sk, int causal)
{
    const long row = blockIdx.x;
    const int  q   = (int)(row % Sq);
    const int  valid = causal ? (q + 1) : Sk;
    const int  wlim  = causal ? (((q >> 7) + 1) << 7) : Sk;
    __half* p = P + row * (long)Sk;
    const int tid = threadIdx.x;
    const int k0 = tid * 8;                     // Sk = 2048 = 256*8
    __shared__ float red[256];

    float r[8];
    if (k0 < wlim) {
        uint4 u = ((const uint4*)p)[tid];
        const __half2* hp = (const __half2*)&u;
        #pragma unroll
        for (int j = 0; j < 4; ++j) {
            float2 f = __half22float2(hp[j]);
            r[2*j] = f.x; r[2*j+1] = f.y;
        }
    } else {
        #pragma unroll
        for (int i = 0; i < 8; ++i) r[i] = -3.0e38f;
    }
    float m = -3.0e38f;
    #pragma unroll
    for (int i = 0; i < 8; ++i) {
        if (k0 + i >= valid) r[i] = -3.0e38f;
        m = fmaxf(m, r[i]);
    }
    red[tid] = m; __syncthreads();
    for (int st = 128; st > 0; st >>= 1) {
        if (tid < st) red[tid] = fmaxf(red[tid], red[tid + st]);
        __syncthreads();
    }
    m = red[0]; __syncthreads();

    float s = 0.0f;
    #pragma unroll
    for (int i = 0; i < 8; ++i) {
        r[i] = (r[i] > -1.0e38f) ? __expf(r[i] - m) : 0.0f;
        s += r[i];
    }
    red[tid] = s; __syncthreads();
    for (int st = 128; st > 0; st >>= 1) {
        if (tid < st) red[tid] += red[tid + st];
        __syncthreads();
    }
    const float inv = 1.0f / red[0];

    if (k0 < wlim) {                            // 8 | 128 so the whole uint4 is in/out
        uint4 o;
        __half2* ho = (__half2*)&o;
        #pragma unroll
        for (int j = 0; j < 4; ++j)
            ho[j] = __floats2half2_rn(r[2*j] * inv, r[2*j+1] * inv);
        ((uint4*)p)[tid] = o;
    }
}

// ---------------- out = LayerNorm(R + X)*gamma + beta; X fp16; optional fp16 copy ----------
template<bool HC>
__global__ void add_ln_kernel(const float* __restrict__ R, const __half* __restrict__ X,
                              const float* __restrict__ g, const float* __restrict__ b,
                              float* __restrict__ O, __half* __restrict__ Oh)
{
    const int  tid = threadIdx.x;
    const long row = blockIdx.x;
    const float4 rv = ((const float4*)(R + row * DD))[tid];
    const uint2 xu = ((const uint2*)(X + row * DD))[tid];
    const float2 x0 = __half22float2(*(const __half2*)&xu.x);
    const float2 x1 = __half22float2(*(const __half2*)&xu.y);
    float v[4] = {rv.x + x0.x, rv.y + x0.y, rv.z + x1.x, rv.w + x1.y};

    float s  = v[0] + v[1] + v[2] + v[3];
    float sq = v[0]*v[0] + v[1]*v[1] + v[2]*v[2] + v[3]*v[3];
    __shared__ float rs[256], rq[256];
    rs[tid] = s; rq[tid] = sq; __syncthreads();
    for (int st = 128; st > 0; st >>= 1) {
        if (tid < st) { rs[tid] += rs[tid + st]; rq[tid] += rq[tid + st]; }
        __syncthreads();
    }
    const float mu  = rs[0] * (1.0f / DD);
    const float var = rq[0] * (1.0f / DD) - mu * mu;
    const float inv = rsqrtf(var + 1e-5f);

    const float4 gv = ((const float4*)g)[tid];
    const float4 bv = ((const float4*)b)[tid];
    float4 o;
    o.x = (v[0] - mu) * inv * gv.x + bv.x;
    o.y = (v[1] - mu) * inv * gv.y + bv.y;
    o.z = (v[2] - mu) * inv * gv.z + bv.z;
    o.w = (v[3] - mu) * inv * gv.w + bv.w;
    ((float4*)(O + row * DD))[tid] = o;
    if (HC) {
        __half2 h0 = __floats2half2_rn(o.x, o.y);
        __half2 h1 = __floats2half2_rn(o.z, o.w);
        uint2 u;
        u.x = *(const uint32_t*)&h0;
        u.y = *(const uint32_t*)&h1;
        ((uint2*)(Oh + row * DD))[tid] = u;
    }
}

// ---------------- launch ----------------
extern "C" void kernel_launch(void* const* d_in, const int* in_sizes, int n_in,
                              void* d_out, int out_size)
{
    (void)in_sizes; (void)n_in; (void)out_size;
    const float* y    = (const float*)d_in[0];
    const float* Z    = (const float*)d_in[1];
    const float* Wff1 = (const float*)d_in[8];
    const float* bff1 = (const float*)d_in[9];
    const float* Wff2 = (const float*)d_in[10];
    const float* bff2 = (const float*)d_in[11];
    const float* g1   = (const float*)d_in[12];
    const float* be1  = (const float*)d_in[13];
    const float* g2   = (const float*)d_in[14];
    const float* be2  = (const float*)d_in[15];
    const float* g3   = (const float*)d_in[16];
    const float* be3  = (const float*)d_in[17];
    float* out = (float*)d_out;

    __half *W, *Wf1, *Wf2, *yc, *Zc, *QKV, *P, *At, *y1h, *y2h, *H;
    float *y1, *y2;
    cudaGetSymbolAddress((void**)&W,   g_W);
    cudaGetSymbolAddress((void**)&Wf1, g_Wf1);
    cudaGetSymbolAddress((void**)&Wf2, g_Wf2);
    cudaGetSymbolAddress((void**)&yc,  g_yc);
    cudaGetSymbolAddress((void**)&Zc,  g_Zc);
    cudaGetSymbolAddress((void**)&QKV, g_QKV);
    cudaGetSymbolAddress((void**)&P,   g_P);
    cudaGetSymbolAddress((void**)&At,  g_At);
    cudaGetSymbolAddress((void**)&y1,  g_y1);
    cudaGetSymbolAddress((void**)&y2,  g_y2);
    cudaGetSymbolAddress((void**)&y1h, g_y1h);
    cudaGetSymbolAddress((void**)&y2h, g_y2h);
    cudaGetSymbolAddress((void**)&H,   g_H);

    cudaFuncSetAttribute(tgemm<__half,true, false,false,false,false>, cudaFuncAttributeMaxDynamicSharedMemorySize, SMEM_BYTES);
    cudaFuncSetAttribute(tgemm<__half,true, true, false,false,false>, cudaFuncAttributeMaxDynamicSharedMemorySize, SMEM_BYTES);
    cudaFuncSetAttribute(tgemm<__half,false,false,false,false,true >, cudaFuncAttributeMaxDynamicSharedMemorySize, SMEM_BYTES);
    cudaFuncSetAttribute(tgemm<__half,false,false,false,false,false>, cudaFuncAttributeMaxDynamicSharedMemorySize, SMEM_BYTES);
    cudaFuncSetAttribute(tgemm<__half,true, false,true, true, false>, cudaFuncAttributeMaxDynamicSharedMemorySize, SMEM_BYTES);
    cudaFuncSetAttribute(tgemm<__half,true, false,true, false,false>, cudaFuncAttributeMaxDynamicSharedMemorySize, SMEM_BYTES);

    const dim3 tht(32, 8);
    // ---- pre-pass: fp16 copies of activations; transposed fp16 weights ----
    cvt2_h<<<dim3(1184, 1, 2), 256>>>((const float4*)y, (uint2*)yc,
                                      (const float4*)Z, (uint2*)Zc, RD / 4);
    Ptr6 w6 = {{ (const float*)d_in[2], (const float*)d_in[3], (const float*)d_in[4],
                 (const float*)d_in[5], (const float*)d_in[6], (const float*)d_in[7] }};
    trans6_kernel<<<dim3(32, 32, 6), tht>>>(w6, W);
    trans_kernel<<<dim3(128, 32), tht>>>(Wff1, Wf1, DD, FFD);   // -> [FF,D]
    trans_kernel<<<dim3(32, 128), tht>>>(Wff2, Wf2, FFD, DD);   // -> [D,FF]

    const dim3 th(256);
    const dim3 gProj3(DD / 128, ROWS / 128, 3);
    const dim3 gProj1(DD / 128, ROWS / 128, 1);
    const dim3 gProj2(DD / 128, ROWS / 128, 2);
    const dim3 gScore(SS / 128, SS / 128, BB);
    const dim3 gAttnV(DD / 128, SS / 128, BB);
    const dim3 gFF1(FFD / 128, ROWS / 128);
    const dim3 gFF2(DD / 128, ROWS / 128);
    const float ascale = 1.0f / 32.0f;            // 1/sqrt(1024)
    const long sQK = (long)SS * DD;
    const long sSc = (long)SS * SS;
    __half* Q  = QKV;
    __half* Kp = QKV + (long)RD;
    __half* V  = QKV + 2L * RD;

    // ---- block 1: causal self-attention + add&norm ----
    tgemm<__half,true, false,false,false,false><<<gProj3, th, SMEM_BYTES>>>(yc, W, nullptr, QKV, DD, DD, 1.0f, 0, DSQ, RD);
    tgemm<__half,true, true, false,false,false><<<gScore, th, SMEM_BYTES>>>(Q, Kp, nullptr, P, SS, DD, ascale, sQK, sQK, sSc);
    softmax_kernel<<<BB * SS, 256>>>(P, SS, SS, 1);
    tgemm<__half,false,false,false,false,true ><<<gAttnV, th, SMEM_BYTES>>>(P, V, nullptr, At, DD, SS, 1.0f, sSc, sQK, sQK);
    add_ln_kernel<true><<<ROWS, 256>>>(y, At, g1, be1, y1, y1h);

    // ---- block 2: cross-attention + add&norm ----
    tgemm<__half,true, false,false,false,false><<<gProj1, th, SMEM_BYTES>>>(y1h, W + 3L*DSQ, nullptr, Q,  DD, DD, 1.0f, 0, DSQ, RD);
    tgemm<__half,true, false,false,false,false><<<gProj2, th, SMEM_BYTES>>>(Zc,  W + 4L*DSQ, nullptr, Kp, DD, DD, 1.0f, 0, DSQ, RD);
    tgemm<__half,true, false,false,false,false><<<gScore, th, SMEM_BYTES>>>(Q, Kp, nullptr, P, SS, DD, ascale, sQK, sQK, sSc);
    softmax_kernel<<<BB * SS, 256>>>(P, SS, SS, 0);
    tgemm<__half,false,false,false,false,false><<<gAttnV, th, SMEM_BYTES>>>(P, V, nullptr, At, DD, SS, 1.0f, sSc, sQK, sQK);
    add_ln_kernel<true><<<ROWS, 256>>>(y1, At, g2, be2, y2, y2h);

    // ---- FFN + add&norm ----
    tgemm<__half,true, false,true, true, false><<<gFF1, th, SMEM_BYTES>>>(y2h, Wf1, bff1, H,  FFD, DD,  1.0f, 0, 0, 0);
    tgemm<__half,true, false,true, false,false><<<gFF2, th, SMEM_BYTES>>>(H,   Wf2, bff2, At, DD,  FFD, 1.0f, 0, 0, 0);
    add_ln_kernel<false><<<ROWS, 256>>>(y2, At, g3, be3, out, nullptr);
}

// round 16
// speedup vs baseline: 1.0985x; 1.0072x over previous
#include <cuda_runtime.h>
#include <cuda_fp16.h>
#include <math.h>
#include <stdint.h>

#define BB 4
#define SS 2048
#define DD 1024
#define FFD 4096
#define ROWS (BB*SS)   // 8192
#define DSQ (DD*DD)
#define RD  (ROWS*DD)

// ---------------- scratch (device globals: no allocation) ----------------
__device__ __half g_W  [6*DSQ];      // transposed [Q1,K1,V1,K2,V2,Q2] ([N,K]) fp16
__device__ __half g_Wf1[FFD*DD];     // Wff1^T fp16
__device__ __half g_Wf2[DD*FFD];     // Wff2^T fp16
__device__ __half g_act[2*RD];       // yc | Zc fp16
__device__ __half g_QKV[5*RD];       // Q1,K1,V1,K2,V2 (Q2 reuses slot 0)
__device__ __half g_P  [(long)BB*SS*SS];  // scores -> probs fp16 (in-place softmax, 32 MB)
__device__ __half g_At [RD];         // attention / FFN branch output, fp16
__device__ float  g_y1 [RD];
__device__ float  g_y2 [RD];
__device__ __half g_y1h[RD];
__device__ __half g_y2h[RD];
__device__ __half g_H  [ROWS*FFD];

// ---------------- helpers ----------------
__device__ __forceinline__ uint32_t smem_u32(const void* p) {
    uint32_t a;
    asm("{ .reg .u64 t; cvta.to.shared.u64 t, %1; cvt.u32.u64 %0, t; }" : "=r"(a) : "l"(p));
    return a;
}
__device__ __forceinline__ void mma_f16(float (&d)[4], const uint32_t (&a)[4], const uint32_t (&b)[2]) {
    asm volatile("mma.sync.aligned.m16n8k16.row.col.f32.f16.f16.f32 "
                 "{%0,%1,%2,%3}, {%4,%5,%6,%7}, {%8,%9}, {%0,%1,%2,%3};"
                 : "+f"(d[0]), "+f"(d[1]), "+f"(d[2]), "+f"(d[3])
                 : "r"(a[0]), "r"(a[1]), "r"(a[2]), "r"(a[3]), "r"(b[0]), "r"(b[1]));
}
#define CP16(dst, src) asm volatile("cp.async.cg.shared.global [%0], [%1], 16;" :: "r"(dst), "l"(src))
#define CP_COMMIT()    asm volatile("cp.async.commit_group;" ::: "memory")
#define CP_WAIT(n)     asm volatile("cp.async.wait_group %0;" :: "n"(n) : "memory")
#define LDSM4(d0,d1,d2,d3,a) \
    asm volatile("ldmatrix.sync.aligned.m8n8.x4.shared.b16 {%0,%1,%2,%3}, [%4];" \
                 : "=r"(d0),"=r"(d1),"=r"(d2),"=r"(d3) : "r"(a))
#define LDSM4T(d0,d1,d2,d3,a) \
    asm volatile("ldmatrix.sync.aligned.m8n8.x4.trans.shared.b16 {%0,%1,%2,%3}, [%4];" \
                 : "=r"(d0),"=r"(d1),"=r"(d2),"=r"(d3) : "r"(a))

// smem: per stage A[128 rows x 144B]; B: TB [128 x 144B] or NN [64 k-rows x 272B]
#define RBYTES  144
#define NBYTES  272
#define A_BYTES (128*RBYTES)            // 18432
#define B_BYTES 18432                   // max(128*144, 64*272=17408)
#define STAGE_BYTES (A_BYTES + B_BYTES) // 36864
#define SMEM_BYTES (3*STAGE_BYTES)      // 110592  (x2 CTAs = 221184 <= 228KB)

template<bool TRB>
__device__ __forceinline__ void issue_stage(uint32_t sA, uint32_t sB,
    const __half* __restrict__ A, const __half* __restrict__ Bm,
    int m0, int n0, int k0, int N, int K, int tid)
{
    #pragma unroll
    for (int i = 0; i < 4; ++i) {            // A: 128 rows x 8 16B-chunks (64 halves of k)
        int pos = tid + i * 256;
        int row = pos >> 3, kq = pos & 7;
        CP16(sA + (uint32_t)(row * RBYTES + kq * 16),
             &A[(long)(m0 + row) * K + k0 + kq * 8]);
    }
    if (TRB) {
        #pragma unroll
        for (int i = 0; i < 4; ++i) {        // B[N,K]: 128 n-rows x 8 chunks
            int pos = tid + i * 256;
            int row = pos >> 3, kq = pos & 7;
            CP16(sB + (uint32_t)(row * RBYTES + kq * 16),
                 &Bm[(long)(n0 + row) * K + k0 + kq * 8]);
        }
    } else {
        #pragma unroll
        for (int i = 0; i < 4; ++i) {        // B[K,N]: 64 k-rows x 16 chunks (128 halves of n)
            int pos = tid + i * 256;
            int row = pos >> 4, cq = pos & 15;
            CP16(sB + (uint32_t)(row * NBYTES + cq * 16),
                 &Bm[(long)(k0 + row) * N + n0 + cq * 8]);
        }
    }
    CP_COMMIT();
}

// ---------------- fp16 HMMA GEMM: C[M,N] = A[M,K]*op(B), tile 128x128xK64, 8 warps, 2 CTA/SM
// TRB: B is [N,K] (C=A*B^T). else B is [K,N] (C=A*B, trans-ldmatrix path).
// CAUSAL: skip tiles above diagonal. CLIPK: K stops at m0+128 (+ heavy-first y order).
// A-select: z < zsplit -> A0 + z*sA_ ; z >= zsplit -> A1 (no stride).
template<typename OT, bool TRB, bool CAUSAL, bool BIAS, bool RELU, bool CLIPK>
__global__ void __launch_bounds__(256, 2)
tgemm(const __half* __restrict__ A0, const __half* __restrict__ A1,
      const __half* __restrict__ Bm0,
      const float* __restrict__ bias, OT* __restrict__ C0,
      int N, int K, float scale, long sA_, long sB_, long sC_, int zsplit)
{
    const int by = CLIPK ? ((int)gridDim.y - 1 - (int)blockIdx.y) : (int)blockIdx.y;
    const int m0 = by * 128, n0 = blockIdx.x * 128;
    if (CAUSAL && n0 > m0 + 127) return;
    const int z = blockIdx.z;
    const __half* A  = (z < zsplit) ? (A0 + (long)z * sA_) : A1;
    const __half* Bm = Bm0 + (long)z * sB_;
    OT* C = C0 + (long)z * sC_;

    extern __shared__ __align__(16) char smc[];
    const uint32_t sb = smem_u32(smc);
    const int tid = threadIdx.x, lane = tid & 31, wid = tid >> 5;
    const int wm = (wid & 1) * 64;          // 2 warps in M
    const int wn = (wid >> 1) * 32;         // 4 warps in N
    const int gid = lane >> 2, tg = lane & 3;
    // ldmatrix per-lane offsets (bytes)
    const uint32_t offA = (uint32_t)(wm + (lane & 15)) * RBYTES + ((lane >> 4) & 1) * 16;
    const uint32_t offB = (uint32_t)(wn + (lane & 7) + ((lane >> 4) & 1) * 8) * RBYTES
                        + ((lane >> 3) & 1) * 16;                      // TB path
    const uint32_t offBn = (uint32_t)((lane & 7) + ((lane >> 3) & 1) * 8) * NBYTES
                         + (uint32_t)wn * 2 + ((lane >> 4) & 1) * 16;  // NN path

    int Keff = K;
    if (CLIPK) { int km = m0 + 128; Keff = (km < K) ? km : K; }
    const int nch = Keff >> 6;              // K-chunks of 64

    float acc[4][4][4];
    #pragma unroll
    for (int mt = 0; mt < 4; ++mt)
        #pragma unroll
        for (int nt = 0; nt < 4; ++nt)
            #pragma unroll
            for (int j = 0; j < 4; ++j) acc[mt][nt][j] = 0.0f;

    issue_stage<TRB>(sb, sb + A_BYTES, A, Bm, m0, n0, 0, N, K, tid);
    if (nch > 1)
        issue_stage<TRB>(sb + STAGE_BYTES, sb + STAGE_BYTES + A_BYTES, A, Bm, m0, n0, 64, N, K, tid);

    for (int c = 0; c < nch; ++c) {
        if (c + 2 <= nch) CP_WAIT(1); else CP_WAIT(0);
        __syncthreads();
        if (c + 2 < nch) {
            const uint32_t off = (uint32_t)((c + 2) % 3) * STAGE_BYTES;
            issue_stage<TRB>(sb + off, sb + off + A_BYTES, A, Bm, m0, n0, (c + 2) << 6, N, K, tid);
        }
        const uint32_t stA = sb + (uint32_t)(c % 3) * STAGE_BYTES;
        const uint32_t stB = stA + A_BYTES;

        // B-fragment loader for k-step ks (double-buffered across ksteps)
        auto load_b = [&](uint32_t (&b)[4][2], int ks) {
            if (TRB) {
                const uint32_t kby = (uint32_t)ks * 32;
                #pragma unroll
                for (int ntp = 0; ntp < 2; ++ntp)
                    LDSM4(b[2*ntp][0], b[2*ntp][1], b[2*ntp+1][0], b[2*ntp+1][1],
                          stB + offB + (uint32_t)(ntp * 16 * RBYTES) + kby);
            } else {
                const uint32_t kof = (uint32_t)(ks * 16) * NBYTES;
                #pragma unroll
                for (int ntp = 0; ntp < 2; ++ntp)
                    LDSM4T(b[2*ntp][0], b[2*ntp][1], b[2*ntp+1][0], b[2*ntp+1][1],
                           stB + offBn + kof + (uint32_t)(ntp * 32));
            }
        };

        uint32_t bf[2][4][2];
        load_b(bf[0], 0);
        #pragma unroll
        for (int ks = 0; ks < 4; ++ks) {
            if (ks < 3) load_b(bf[(ks + 1) & 1], ks + 1);
            const uint32_t kby = (uint32_t)ks * 32;
            #pragma unroll
            for (int mt = 0; mt < 4; ++mt) {
                uint32_t a[4];
                LDSM4(a[0], a[1], a[2], a[3],
                      stA + offA + (uint32_t)(mt * 16 * RBYTES) + kby);
                #pragma unroll
                for (int nt = 0; nt < 4; ++nt) mma_f16(acc[mt][nt], a, bf[ks & 1][nt]);
            }
        }
    }

    // ---- epilogue ----
    #pragma unroll
    for (int mt = 0; mt < 4; ++mt) {
        const long r0 = m0 + wm + mt * 16 + gid;
        #pragma unroll
        for (int nt = 0; nt < 4; ++nt) {
            const int col = n0 + wn + nt * 8 + 2 * tg;
            float v0 = acc[mt][nt][0] * scale;
            float v1 = acc[mt][nt][1] * scale;
            float v2 = acc[mt][nt][2] * scale;
            float v3 = acc[mt][nt][3] * scale;
            if (BIAS) {
                float b0 = bias[col], b1 = bias[col + 1];
                v0 += b0; v1 += b1; v2 += b0; v3 += b1;
            }
            if (RELU) {
                v0 = fmaxf(v0, 0.0f); v1 = fmaxf(v1, 0.0f);
                v2 = fmaxf(v2, 0.0f); v3 = fmaxf(v3, 0.0f);
            }
            if constexpr (sizeof(OT) == 2) {
                *(__half2*)&C[r0 * (long)N + col]       = __floats2half2_rn(v0, v1);
                *(__half2*)&C[(r0 + 8) * (long)N + col] = __floats2half2_rn(v2, v3);
            } else {
                *(float2*)&C[r0 * (long)N + col]       = make_float2(v0, v1);
                *(float2*)&C[(r0 + 8) * (long)N + col] = make_float2(v2, v3);
            }
        }
    }
}

// ---------------- fp32 -> fp16 copies, two tensors in one launch ----------------
__global__ void cvt2_h(const float4* __restrict__ s0, uint2* __restrict__ d0,
                       const float4* __restrict__ s1, uint2* __restrict__ d1, int n4)
{
    const float4* s = blockIdx.z ? s1 : s0;
    uint2* d = blockIdx.z ? d1 : d0;
    for (int i = blockIdx.x * blockDim.x + threadIdx.x; i < n4; i += gridDim.x * blockDim.x) {
        float4 v = s[i];
        __half2 h0 = __floats2half2_rn(v.x, v.y);
        __half2 h1 = __floats2half2_rn(v.z, v.w);
        uint2 u;
        u.x = *(const uint32_t*)&h0;
        u.y = *(const uint32_t*)&h1;
        d[i] = u;
    }
}

// ---------------- transpose to fp16: src[R,C] -> dst[C,R] ----------------
__global__ void trans_kernel(const float* __restrict__ src, __half* __restrict__ dst,
                             int R, int C)
{
    __shared__ float t[32][33];
    const int c0 = blockIdx.x * 32, r0 = blockIdx.y * 32;
    const int x = threadIdx.x, y = threadIdx.y;      // 32x8
    #pragma unroll
    for (int i = 0; i < 32; i += 8)
        t[y + i][x] = src[(long)(r0 + y + i) * C + c0 + x];
    __syncthreads();
    #pragma unroll
    for (int i = 0; i < 32; i += 8)
        dst[(long)(c0 + y + i) * R + r0 + x] = __float2half_rn(t[x][y + i]);
}

// ---------------- batched 1024x1024 transpose of the six attention weights ----------------
struct Ptr6 { const float* p[6]; };
__global__ void trans6_kernel(Ptr6 src, __half* __restrict__ dst)
{
    __shared__ float t[32][33];
    const float* s = src.p[blockIdx.z];
    __half* d = dst + (long)blockIdx.z * DSQ;
    const int c0 = blockIdx.x * 32, r0 = blockIdx.y * 32;
    const int x = threadIdx.x, y = threadIdx.y;
    #pragma unroll
    for (int i = 0; i < 32; i += 8)
        t[y + i][x] = s[(long)(r0 + y + i) * DD + c0 + x];
    __syncthreads();
    #pragma unroll
    for (int i = 0; i < 32; i += 8)
        d[(long)(c0 + y + i) * DD + r0 + x] = __float2half_rn(t[x][y + i]);
}

// ---------------- in-place row softmax on fp16 scores/probs ----------------
// One uint4 (8 halves) per thread; causal: loads/stores only below the 128-aligned limit.
__global__ void softmax_kernel(__half* __restrict__ P, int Sq, int Sk, int causal)
{
    const long row = blockIdx.x;
    const int  q   = (int)(row % Sq);
    const int  valid = causal ? (q + 1) : Sk;
    const int  wlim  = causal ? (((q >> 7) + 1) << 7) : Sk;
    __half* p = P + row * (long)Sk;
    const int tid = threadIdx.x;
    const int k0 = tid * 8;                     // Sk = 2048 = 256*8
    __shared__ float red[256];

    float r[8];
    if (k0 < wlim) {
        uint4 u = ((const uint4*)p)[tid];
        const __half2* hp = (const __half2*)&u;
        #pragma unroll
        for (int j = 0; j < 4; ++j) {
            float2 f = __half22float2(hp[j]);
            r[2*j] = f.x; r[2*j+1] = f.y;
        }
    } else {
        #pragma unroll
        for (int i = 0; i < 8; ++i) r[i] = -3.0e38f;
    }
    float m = -3.0e38f;
    #pragma unroll
    for (int i = 0; i < 8; ++i) {
        if (k0 + i >= valid) r[i] = -3.0e38f;
        m = fmaxf(m, r[i]);
    }
    red[tid] = m; __syncthreads();
    for (int st = 128; st > 0; st >>= 1) {
        if (tid < st) red[tid] = fmaxf(red[tid], red[tid + st]);
        __syncthreads();
    }
    m = red[0]; __syncthreads();

    float s = 0.0f;
    #pragma unroll
    for (int i = 0; i < 8; ++i) {
        r[i] = (r[i] > -1.0e38f) ? __expf(r[i] - m) : 0.0f;
        s += r[i];
    }
    red[tid] = s; __syncthreads();
    for (int st = 128; st > 0; st >>= 1) {
        if (tid < st) red[tid] += red[tid + st];
        __syncthreads();
    }
    const float inv = 1.0f / red[0];

    if (k0 < wlim) {                            // 8 | 128 so the whole uint4 is in/out
        uint4 o;
        __half2* ho = (__half2*)&o;
        #pragma unroll
        for (int j = 0; j < 4; ++j)
            ho[j] = __floats2half2_rn(r[2*j] * inv, r[2*j+1] * inv);
        ((uint4*)p)[tid] = o;
    }
}

// ---------------- out = LayerNorm(R + X)*gamma + beta; X fp16; optional fp16 copy ----------
template<bool HC>
__global__ void add_ln_kernel(const float* __restrict__ R, const __half* __restrict__ X,
                              const float* __restrict__ g, const float* __restrict__ b,
                              float* __restrict__ O, __half* __restrict__ Oh)
{
    const int  tid = threadIdx.x;
    const long row = blockIdx.x;
    const float4 rv = ((const float4*)(R + row * DD))[tid];
    const uint2 xu = ((const uint2*)(X + row * DD))[tid];
    const float2 x0 = __half22float2(*(const __half2*)&xu.x);
    const float2 x1 = __half22float2(*(const __half2*)&xu.y);
    float v[4] = {rv.x + x0.x, rv.y + x0.y, rv.z + x1.x, rv.w + x1.y};

    float s  = v[0] + v[1] + v[2] + v[3];
    float sq = v[0]*v[0] + v[1]*v[1] + v[2]*v[2] + v[3]*v[3];
    __shared__ float rs[256], rq[256];
    rs[tid] = s; rq[tid] = sq; __syncthreads();
    for (int st = 128; st > 0; st >>= 1) {
        if (tid < st) { rs[tid] += rs[tid + st]; rq[tid] += rq[tid + st]; }
        __syncthreads();
    }
    const float mu  = rs[0] * (1.0f / DD);
    const float var = rq[0] * (1.0f / DD) - mu * mu;
    const float inv = rsqrtf(var + 1e-5f);

    const float4 gv = ((const float4*)g)[tid];
    const float4 bv = ((const float4*)b)[tid];
    float4 o;
    o.x = (v[0] - mu) * inv * gv.x + bv.x;
    o.y = (v[1] - mu) * inv * gv.y + bv.y;
    o.z = (v[2] - mu) * inv * gv.z + bv.z;
    o.w = (v[3] - mu) * inv * gv.w + bv.w;
    ((float4*)(O + row * DD))[tid] = o;
    if (HC) {
        __half2 h0 = __floats2half2_rn(o.x, o.y);
        __half2 h1 = __floats2half2_rn(o.z, o.w);
        uint2 u;
        u.x = *(const uint32_t*)&h0;
        u.y = *(const uint32_t*)&h1;
        ((uint2*)(Oh + row * DD))[tid] = u;
    }
}

// ---------------- launch ----------------
extern "C" void kernel_launch(void* const* d_in, const int* in_sizes, int n_in,
                              void* d_out, int out_size)
{
    (void)in_sizes; (void)n_in; (void)out_size;
    const float* y    = (const float*)d_in[0];
    const float* Z    = (const float*)d_in[1];
    const float* Wff1 = (const float*)d_in[8];
    const float* bff1 = (const float*)d_in[9];
    const float* Wff2 = (const float*)d_in[10];
    const float* bff2 = (const float*)d_in[11];
    const float* g1   = (const float*)d_in[12];
    const float* be1  = (const float*)d_in[13];
    const float* g2   = (const float*)d_in[14];
    const float* be2  = (const float*)d_in[15];
    const float* g3   = (const float*)d_in[16];
    const float* be3  = (const float*)d_in[17];
    float* out = (float*)d_out;

    __half *W, *Wf1, *Wf2, *act, *QKV, *P, *At, *y1h, *y2h, *H;
    float *y1, *y2;
    cudaGetSymbolAddress((void**)&W,   g_W);
    cudaGetSymbolAddress((void**)&Wf1, g_Wf1);
    cudaGetSymbolAddress((void**)&Wf2, g_Wf2);
    cudaGetSymbolAddress((void**)&act, g_act);
    cudaGetSymbolAddress((void**)&QKV, g_QKV);
    cudaGetSymbolAddress((void**)&P,   g_P);
    cudaGetSymbolAddress((void**)&At,  g_At);
    cudaGetSymbolAddress((void**)&y1,  g_y1);
    cudaGetSymbolAddress((void**)&y2,  g_y2);
    cudaGetSymbolAddress((void**)&y1h, g_y1h);
    cudaGetSymbolAddress((void**)&y2h, g_y2h);
    cudaGetSymbolAddress((void**)&H,   g_H);
    __half* yc = act;
    __half* Zc = act + (long)RD;

    cudaFuncSetAttribute(tgemm<__half,true, false,false,false,false>, cudaFuncAttributeMaxDynamicSharedMemorySize, SMEM_BYTES);
    cudaFuncSetAttribute(tgemm<__half,true, true, false,false,false>, cudaFuncAttributeMaxDynamicSharedMemorySize, SMEM_BYTES);
    cudaFuncSetAttribute(tgemm<__half,false,false,false,false,true >, cudaFuncAttributeMaxDynamicSharedMemorySize, SMEM_BYTES);
    cudaFuncSetAttribute(tgemm<__half,false,false,false,false,false>, cudaFuncAttributeMaxDynamicSharedMemorySize, SMEM_BYTES);
    cudaFuncSetAttribute(tgemm<__half,true, false,true, true, false>, cudaFuncAttributeMaxDynamicSharedMemorySize, SMEM_BYTES);
    cudaFuncSetAttribute(tgemm<__half,true, false,true, false,false>, cudaFuncAttributeMaxDynamicSharedMemorySize, SMEM_BYTES);

    const dim3 tht(32, 8);
    // ---- pre-pass: fp16 copies of activations; transposed fp16 weights ----
    cvt2_h<<<dim3(1184, 1, 2), 256>>>((const float4*)y, (uint2*)yc,
                                      (const float4*)Z, (uint2*)Zc, RD / 4);
    // W destination order: Q1, K1, V1, K2, V2, Q2
    Ptr6 w6 = {{ (const float*)d_in[2], (const float*)d_in[3], (const float*)d_in[4],
                 (const float*)d_in[6], (const float*)d_in[7], (const float*)d_in[5] }};
    trans6_kernel<<<dim3(32, 32, 6), tht>>>(w6, W);
    trans_kernel<<<dim3(128, 32), tht>>>(Wff1, Wf1, DD, FFD);   // -> [FF,D]
    trans_kernel<<<dim3(32, 128), tht>>>(Wff2, Wf2, FFD, DD);   // -> [D,FF]

    const dim3 th(256);
    const dim3 gProj5(DD / 128, ROWS / 128, 5);   // Q1,K1,V1 from yc; K2,V2 from Zc
    const dim3 gProj1(DD / 128, ROWS / 128, 1);
    const dim3 gScore(SS / 128, SS / 128, BB);
    const dim3 gAttnV(DD / 128, SS / 128, BB);
    const dim3 gFF1(FFD / 128, ROWS / 128);
    const dim3 gFF2(DD / 128, ROWS / 128);
    const float ascale = 1.0f / 32.0f;            // 1/sqrt(1024)
    const long sQK = (long)SS * DD;
    const long sSc = (long)SS * SS;
    const int  ZBIG = 0x7FFFFFFF;
    __half* Q1 = QKV;
    __half* K1 = QKV + (long)RD;
    __half* V1 = QKV + 2L * RD;
    __half* K2 = QKV + 3L * RD;
    __half* V2 = QKV + 4L * RD;
    __half* Q2 = QKV;                             // reuse slot 0 (Q1 dead after score1)

    // ---- all input-derived projections in ONE launch: z<3 read yc, z>=3 read Zc ----
    tgemm<__half,true, false,false,false,false><<<gProj5, th, SMEM_BYTES>>>(yc, Zc, W, nullptr, QKV, DD, DD, 1.0f, 0, DSQ, RD, 3);

    // ---- block 1: causal self-attention + add&norm ----
    tgemm<__half,true, true, false,false,false><<<gScore, th, SMEM_BYTES>>>(Q1, nullptr, K1, nullptr, P, SS, DD, ascale, sQK, sQK, sSc, ZBIG);
    softmax_kernel<<<BB * SS, 256>>>(P, SS, SS, 1);
    tgemm<__half,false,false,false,false,true ><<<gAttnV, th, SMEM_BYTES>>>(P, nullptr, V1, nullptr, At, DD, SS, 1.0f, sSc, sQK, sQK, ZBIG);
    add_ln_kernel<true><<<ROWS, 256>>>(y, At, g1, be1, y1, y1h);

    // ---- block 2: cross-attention + add&norm (K2/V2 already computed) ----
    tgemm<__half,true, false,false,false,false><<<gProj1, th, SMEM_BYTES>>>(y1h, nullptr, W + 5L*DSQ, nullptr, Q2, DD, DD, 1.0f, 0, DSQ, RD, ZBIG);
    tgemm<__half,true, false,false,false,false><<<gScore, th, SMEM_BYTES>>>(Q2, nullptr, K2, nullptr, P, SS, DD, ascale, sQK, sQK, sSc, ZBIG);
    softmax_kernel<<<BB * SS, 256>>>(P, SS, SS, 0);
    tgemm<__half,false,false,false,false,false><<<gAttnV, th, SMEM_BYTES>>>(P, nullptr, V2, nullptr, At, DD, SS, 1.0f, sSc, sQK, sQK, ZBIG);
    add_ln_kernel<true><<<ROWS, 256>>>(y1, At, g2, be2, y2, y2h);

    // ---- FFN + add&norm ----
    tgemm<__half,true, false,true, true, false><<<gFF1, th, SMEM_BYTES>>>(y2h, nullptr, Wf1, bff1, H,  FFD, DD,  1.0f, 0, 0, 0, ZBIG);
    tgemm<__half,true, false,true, false,false><<<gFF2, th, SMEM_BYTES>>>(H,   nullptr, Wf2, bff2, At, DD,  FFD, 1.0f, 0, 0, 0, ZBIG);
    add_ln_kernel<false><<<ROWS, 256>>>(y2, At, g3, be3, out, nullptr);
}